// round 16
// baseline (speedup 1.0000x reference)
#include <cuda_runtime.h>
#include <cuda_fp16.h>
#include <cstdint>

#define NN 100000
#define F1 64
#define F2 16
#define EMAX 1600000
#define NBS 391   // ceil(NN/256)

typedef unsigned long long ull;

// Scratch (allocation-free rule: __device__ globals; zero-init at load,
// re-zeroed by k_gather16's epilogue each call)
__device__ int      g_cnt[NN];
__device__ int      g_off[NN];
__device__ int      g_rank[EMAX];    // per-edge rank within its dst bucket (from hist)
__device__ unsigned g_state[512];    // decoupled-lookback: flag<<30 | value
__device__ int      g_srcs[EMAX];
__device__ __half   g_ynh[NN * F1];  // x @ W1n   (fp16 staged)
__device__ float    g_h1[NN * F1];   // y_s = x@W1s + b1, then overwritten with h1
__device__ __half   g_z2h[NN * F2];  // h1 @ W2n  (fp16 staged)

// ---------------- f32x2 packed helpers (sm_100+) ----------------
__device__ __forceinline__ ull pack2(float v) {
    ull r; asm("mov.b64 %0, {%1, %1};" : "=l"(r) : "f"(v)); return r;
}
__device__ __forceinline__ ull packab(float a, float b) {
    ull r; asm("mov.b64 %0, {%1, %2};" : "=l"(r) : "f"(a), "f"(b)); return r;
}
__device__ __forceinline__ ull fma2(ull a, ull b, ull c) {
    ull d; asm("fma.rn.f32x2 %0, %1, %2, %3;" : "=l"(d) : "l"(a), "l"(b), "l"(c)); return d;
}
__device__ __forceinline__ float2 unpack2(ull v) {
    float2 f; asm("mov.b64 {%0, %1}, %2;" : "=f"(f.x), "=f"(f.y) : "l"(v)); return f;
}
__device__ __forceinline__ unsigned h2u(__half2 h) {
    return *reinterpret_cast<unsigned*>(&h);
}
__device__ __forceinline__ void acc_h4(float4& a, uint2 u) {
    float2 f0 = __half22float2(*reinterpret_cast<__half2*>(&u.x));
    float2 f1 = __half22float2(*reinterpret_cast<__half2*>(&u.y));
    a.x += f0.x; a.y += f0.y; a.z += f1.x; a.w += f1.y;
}
// XOR swizzle on float4 index within a 32-float4 (128-float) row.
__device__ __forceinline__ int swz(int f) { return f ^ ((f >> 3) & 3); }

// ================= in-degree histogram + per-edge rank (4 edges/thread) ====
// g_cnt arrives zeroed (BSS on first call; k_gather16 epilogue afterwards).
__global__ void k_hist(const int* __restrict__ dst, int E) {
    int e0 = (blockIdx.x * 256 + threadIdx.x) * 4;
    if (e0 + 3 < E) {
        int4 d4 = *reinterpret_cast<const int4*>(dst + e0);
        int4 r4;
        r4.x = atomicAdd(&g_cnt[d4.x], 1);
        r4.y = atomicAdd(&g_cnt[d4.y], 1);
        r4.z = atomicAdd(&g_cnt[d4.z], 1);
        r4.w = atomicAdd(&g_cnt[d4.w], 1);
        *reinterpret_cast<int4*>(g_rank + e0) = r4;
    } else {
        for (int e = e0; e < E; ++e) g_rank[e] = atomicAdd(&g_cnt[dst[e]], 1);
    }
}

// ================= single-pass exclusive scan (decoupled lookback) =====
#define SMASK 0x3FFFFFFFu
__global__ void k_scan() {
    __shared__ int sm[256];
    __shared__ int s_prev;
    int b = blockIdx.x, t = threadIdx.x;
    int i = b * 256 + t;
    int v = (i < NN) ? g_cnt[i] : 0;
    sm[t] = v;
    __syncthreads();
    for (int d = 1; d < 256; d <<= 1) {
        int a = (t >= d) ? sm[t - d] : 0;
        __syncthreads();
        sm[t] += a;
        __syncthreads();
    }
    int incl = sm[t];
    if (t == 0) {
        unsigned total = (unsigned)sm[255];
        if (b == 0) {
            atomicExch(&g_state[0], (2u << 30) | total);
            s_prev = 0;
        } else {
            atomicExch(&g_state[b], (1u << 30) | total);
            unsigned prev = 0u;
            int j = b - 1;
            while (true) {
                unsigned st = atomicAdd(&g_state[j], 0u);
                unsigned f = st >> 30;
                if (f == 2u) { prev += st & SMASK; break; }
                if (f == 1u) { prev += st & SMASK; --j; }
            }
            atomicExch(&g_state[b], (2u << 30) | ((prev + total) & SMASK));
            s_prev = (int)prev;
        }
    }
    __syncthreads();
    if (i < NN) g_off[i] = s_prev + incl - v;
}

// ================= bucket placement, ATOMIC-FREE (4 edges/thread) =========
__global__ void k_place(const int* __restrict__ src, const int* __restrict__ dst, int E) {
    int e0 = (blockIdx.x * 256 + threadIdx.x) * 4;
    if (e0 + 3 < E) {
        int4 d4 = *reinterpret_cast<const int4*>(dst + e0);
        int4 s4 = *reinterpret_cast<const int4*>(src + e0);
        int4 r4 = *reinterpret_cast<const int4*>(g_rank + e0);
        g_srcs[g_off[d4.x] + r4.x] = s4.x;
        g_srcs[g_off[d4.y] + r4.y] = s4.y;
        g_srcs[g_off[d4.z] + r4.z] = s4.z;
        g_srcs[g_off[d4.w] + r4.w] = s4.w;
    } else {
        for (int e = e0; e < E; ++e)
            g_srcs[g_off[dst[e]] + g_rank[e]] = src[e];
    }
}

// ================= layer-1 projection GEMM (R12-proven single-tile) =======
// y = x[NN x 64] @ [W1s | W1n][64 x 128]. Cols 0..63 -> g_h1 (fp32, bias folded),
// cols 64..127 -> g_ynh (fp16). Weight tile bank-swizzled. Nd=4, 68 regs.
#define P1 68
__global__ void __launch_bounds__(256) k_proj1(
    const float* __restrict__ x,
    const float* __restrict__ Ws, const float* __restrict__ Wn,
    const float* __restrict__ b) {
    extern __shared__ float s[];
    float* sW = s;          // 64 x 128, float4-swizzled rows
    float* sX = s + 8192;   // 64 x P1

    int tid   = threadIdx.x;
    int node0 = blockIdx.x * 64;

    for (int i = tid; i < 2048; i += 256) {  // 64 rows x 32 float4
        int k = i >> 5, c = i & 31;
        float4 v = (c < 16) ? reinterpret_cast<const float4*>(Ws + k * 64)[c]
                            : reinterpret_cast<const float4*>(Wn + k * 64)[c - 16];
        reinterpret_cast<float4*>(sW + k * 128)[swz(c)] = v;
    }
    for (int i = tid; i < 64 * 16; i += 256) {
        int row = i >> 4, c = i & 15;
        int n = node0 + row;
        float4 vx = make_float4(0.f, 0.f, 0.f, 0.f);
        if (n < NN) vx = reinterpret_cast<const float4*>(x + (size_t)n * F1)[c];
        *reinterpret_cast<float4*>(sX + row * P1 + 4 * c) = vx;
    }
    __syncthreads();

    int j8 = (tid & 15) << 3;  // 0..120
    int ng = tid >> 4;         // 0..15
    int rb[4] = { ng * P1, (ng + 16) * P1, (ng + 32) * P1, (ng + 48) * P1 };

    int wo0 = 4 * swz(j8 >> 2);
    int wo1 = 4 * swz((j8 >> 2) + 1);

    ull binit[4] = {0ull, 0ull, 0ull, 0ull};
    if (j8 < 64) {
        float4 bl = *reinterpret_cast<const float4*>(b + j8);
        float4 bh = *reinterpret_cast<const float4*>(b + j8 + 4);
        binit[0] = packab(bl.x, bl.y); binit[1] = packab(bl.z, bl.w);
        binit[2] = packab(bh.x, bh.y); binit[3] = packab(bh.z, bh.w);
    }
    ull ac[4][4];
#pragma unroll
    for (int nn = 0; nn < 4; ++nn)
#pragma unroll
        for (int p = 0; p < 4; ++p) ac[nn][p] = binit[p];

#pragma unroll 2
    for (int k0 = 0; k0 < 64; k0 += 4) {
        float4 xv[4];
#pragma unroll
        for (int nn = 0; nn < 4; ++nn)
            xv[nn] = *reinterpret_cast<const float4*>(sX + rb[nn] + k0);
#pragma unroll
        for (int kk = 0; kk < 4; ++kk) {
            const float* wrow = sW + (k0 + kk) * 128;
            ulonglong2 wA = *reinterpret_cast<const ulonglong2*>(wrow + wo0);
            ulonglong2 wB = *reinterpret_cast<const ulonglong2*>(wrow + wo1);
#pragma unroll
            for (int nn = 0; nn < 4; ++nn) {
                float xs = (kk == 0) ? xv[nn].x : (kk == 1) ? xv[nn].y
                         : (kk == 2) ? xv[nn].z : xv[nn].w;
                ull xx = pack2(xs);
                ac[nn][0] = fma2(xx, wA.x, ac[nn][0]);
                ac[nn][1] = fma2(xx, wA.y, ac[nn][1]);
                ac[nn][2] = fma2(xx, wB.x, ac[nn][2]);
                ac[nn][3] = fma2(xx, wB.y, ac[nn][3]);
            }
        }
    }

    if (j8 < 64) {
#pragma unroll
        for (int nn = 0; nn < 4; ++nn) {
            int gn = node0 + ng + nn * 16;
            if (gn < NN) {
                float2 r0 = unpack2(ac[nn][0]), r1 = unpack2(ac[nn][1]);
                float2 r2 = unpack2(ac[nn][2]), r3 = unpack2(ac[nn][3]);
                float4 o0 = make_float4(r0.x, r0.y, r1.x, r1.y);
                float4 o1 = make_float4(r2.x, r2.y, r3.x, r3.y);
                *reinterpret_cast<float4*>(g_h1 + (size_t)gn * F1 + j8)     = o0;
                *reinterpret_cast<float4*>(g_h1 + (size_t)gn * F1 + j8 + 4) = o1;
            }
        }
    } else {
        int jc = j8 - 64;
#pragma unroll
        for (int nn = 0; nn < 4; ++nn) {
            int gn = node0 + ng + nn * 16;
            if (gn < NN) {
                float2 r0 = unpack2(ac[nn][0]), r1 = unpack2(ac[nn][1]);
                float2 r2 = unpack2(ac[nn][2]), r3 = unpack2(ac[nn][3]);
                uint4 st = make_uint4(h2u(__float22half2_rn(r0)),
                                      h2u(__float22half2_rn(r1)),
                                      h2u(__float22half2_rn(r2)),
                                      h2u(__float22half2_rn(r3)));
                *reinterpret_cast<uint4*>(g_ynh + (size_t)gn * F1 + jc) = st;
            }
        }
    }
}

// ================= layer-1 gather + epilogue ==================
// h1[n] = relu(y_s[n] + (sum ynh[src]) / deg). 16 threads/node, 4 halves each.
__global__ void k_gather_h1() {
    int t = blockIdx.x * 256 + threadIdx.x;
    int n = t >> 4;
    if (n >= NN) return;
    int c4 = (t & 15) << 2;
    int base = g_off[n], cnt = g_cnt[n];
    float4 a = make_float4(0.f, 0.f, 0.f, 0.f);
    int i = 0;
#pragma unroll 2
    for (; i + 4 <= cnt; i += 4) {
        int s0 = g_srcs[base + i];
        int s1 = g_srcs[base + i + 1];
        int s2 = g_srcs[base + i + 2];
        int s3 = g_srcs[base + i + 3];
        uint2 v0 = *reinterpret_cast<const uint2*>(g_ynh + (size_t)s0 * F1 + c4);
        uint2 v1 = *reinterpret_cast<const uint2*>(g_ynh + (size_t)s1 * F1 + c4);
        uint2 v2 = *reinterpret_cast<const uint2*>(g_ynh + (size_t)s2 * F1 + c4);
        uint2 v3 = *reinterpret_cast<const uint2*>(g_ynh + (size_t)s3 * F1 + c4);
        acc_h4(a, v0); acc_h4(a, v1); acc_h4(a, v2); acc_h4(a, v3);
    }
    for (; i < cnt; ++i) {
        int s0 = g_srcs[base + i];
        acc_h4(a, *reinterpret_cast<const uint2*>(g_ynh + (size_t)s0 * F1 + c4));
    }
    float dinv = 1.0f / (float)max(cnt, 1);
    float* p = g_h1 + (size_t)n * F1 + c4;
    float4 ys = *reinterpret_cast<const float4*>(p);
    float4 o;
    o.x = fmaxf(fmaf(a.x, dinv, ys.x), 0.f);
    o.y = fmaxf(fmaf(a.y, dinv, ys.y), 0.f);
    o.z = fmaxf(fmaf(a.z, dinv, ys.z), 0.f);
    o.w = fmaxf(fmaf(a.w, dinv, ys.w), 0.f);
    *reinterpret_cast<float4*>(p) = o;
}

// ================= layer-2 combine: GEMM [NN x 64] @ [64 x 32] =========
// Cols 0..15 -> out (self + bias, fp32), cols 16..31 -> g_z2h (fp16).
#define P2 68
__global__ void __launch_bounds__(256) k_combine2(
    const float* __restrict__ Ws, const float* __restrict__ Wn,
    const float* __restrict__ b, float* __restrict__ out) {
    extern __shared__ float s[];
    float* sW = s;         // 64 x 32
    float* sH = s + 2048;  // 128 x P2
    float* sB = s + 2048 + 128 * P2;  // 16

    int tid   = threadIdx.x;
    int node0 = blockIdx.x * 128;

    {
        int k = tid >> 2, c = tid & 3;
        reinterpret_cast<float4*>(sW + k * 32)[c]      = reinterpret_cast<const float4*>(Ws + k * 16)[c];
        reinterpret_cast<float4*>(sW + k * 32 + 16)[c] = reinterpret_cast<const float4*>(Wn + k * 16)[c];
    }
    if (tid < 16) sB[tid] = b[tid];
    for (int i = tid; i < 128 * 16; i += 256) {
        int row = i >> 4, c = i & 15;
        int n = node0 + row;
        float4 v = make_float4(0.f, 0.f, 0.f, 0.f);
        if (n < NN) v = reinterpret_cast<const float4*>(g_h1 + (size_t)n * F1)[c];
        *reinterpret_cast<float4*>(sH + row * P2 + 4 * c) = v;
    }
    __syncthreads();

    int j8 = (tid & 3) << 3;  // 0,8,16,24
    int ng = tid >> 2;        // 0..63
    int rb[2] = { ng * P2, (ng + 64) * P2 };

    ull ac[2][4];
#pragma unroll
    for (int nn = 0; nn < 2; ++nn)
#pragma unroll
        for (int p = 0; p < 4; ++p) ac[nn][p] = 0ull;

#pragma unroll 4
    for (int k = 0; k < 64; ++k) {
        const float* wp = sW + k * 32 + j8;
        ulonglong2 wA = *reinterpret_cast<const ulonglong2*>(wp);
        ulonglong2 wB = *reinterpret_cast<const ulonglong2*>(wp + 4);
#pragma unroll
        for (int nn = 0; nn < 2; ++nn) {
            ull hh = pack2(sH[rb[nn] + k]);
            ac[nn][0] = fma2(hh, wA.x, ac[nn][0]);
            ac[nn][1] = fma2(hh, wA.y, ac[nn][1]);
            ac[nn][2] = fma2(hh, wB.x, ac[nn][2]);
            ac[nn][3] = fma2(hh, wB.y, ac[nn][3]);
        }
    }

    if (j8 < 16) {
        float4 bl = *reinterpret_cast<const float4*>(sB + j8);
        float4 bh = *reinterpret_cast<const float4*>(sB + j8 + 4);
#pragma unroll
        for (int nn = 0; nn < 2; ++nn) {
            int gn = node0 + ng + nn * 64;
            if (gn < NN) {
                float2 r0 = unpack2(ac[nn][0]), r1 = unpack2(ac[nn][1]);
                float2 r2 = unpack2(ac[nn][2]), r3 = unpack2(ac[nn][3]);
                float4 o0 = make_float4(r0.x + bl.x, r0.y + bl.y, r1.x + bl.z, r1.y + bl.w);
                float4 o1 = make_float4(r2.x + bh.x, r2.y + bh.y, r3.x + bh.z, r3.y + bh.w);
                *reinterpret_cast<float4*>(out + (size_t)gn * F2 + j8)     = o0;
                *reinterpret_cast<float4*>(out + (size_t)gn * F2 + j8 + 4) = o1;
            }
        }
    } else {
        int j = j8 - 16;
#pragma unroll
        for (int nn = 0; nn < 2; ++nn) {
            int gn = node0 + ng + nn * 64;
            if (gn < NN) {
                float2 r0 = unpack2(ac[nn][0]), r1 = unpack2(ac[nn][1]);
                float2 r2 = unpack2(ac[nn][2]), r3 = unpack2(ac[nn][3]);
                uint4 st = make_uint4(h2u(__float22half2_rn(r0)),
                                      h2u(__float22half2_rn(r1)),
                                      h2u(__float22half2_rn(r2)),
                                      h2u(__float22half2_rn(r3)));
                *reinterpret_cast<uint4*>(g_z2h + (size_t)gn * F2 + j) = st;
            }
        }
    }
}

// ================= layer-2 gather + finalize + scratch re-zero ============
__global__ void k_gather16(float* __restrict__ out) {
    int t = blockIdx.x * 256 + threadIdx.x;
    // re-zero lookback state for the NEXT invocation
    if (blockIdx.x == 0 && threadIdx.x < 512) g_state[threadIdx.x] = 0u;
    int n = t >> 2;
    if (n >= NN) return;
    int c4 = (t & 3) << 2;
    int base = g_off[n], cnt = g_cnt[n];
    float4 a = make_float4(0.f, 0.f, 0.f, 0.f);
    int i = 0;
#pragma unroll 2
    for (; i + 4 <= cnt; i += 4) {
        int s0 = g_srcs[base + i];
        int s1 = g_srcs[base + i + 1];
        int s2 = g_srcs[base + i + 2];
        int s3 = g_srcs[base + i + 3];
        uint2 v0 = *reinterpret_cast<const uint2*>(g_z2h + (size_t)s0 * F2 + c4);
        uint2 v1 = *reinterpret_cast<const uint2*>(g_z2h + (size_t)s1 * F2 + c4);
        uint2 v2 = *reinterpret_cast<const uint2*>(g_z2h + (size_t)s2 * F2 + c4);
        uint2 v3 = *reinterpret_cast<const uint2*>(g_z2h + (size_t)s3 * F2 + c4);
        acc_h4(a, v0); acc_h4(a, v1); acc_h4(a, v2); acc_h4(a, v3);
    }
    for (; i < cnt; ++i) {
        int s0 = g_srcs[base + i];
        acc_h4(a, *reinterpret_cast<const uint2*>(g_z2h + (size_t)s0 * F2 + c4));
    }
    // re-zero g_cnt[n] for the next invocation (cnt already read by all 4
    // lanes of this node, same warp, before this store)
    if ((t & 3) == 0) g_cnt[n] = 0;
    float dinv = 1.0f / (float)max(cnt, 1);
    float4 o = *reinterpret_cast<float4*>(out + (size_t)n * F2 + c4);
    o.x = fmaf(a.x, dinv, o.x); o.y = fmaf(a.y, dinv, o.y);
    o.z = fmaf(a.z, dinv, o.z); o.w = fmaf(a.w, dinv, o.w);
    *reinterpret_cast<float4*>(out + (size_t)n * F2 + c4) = o;
}

extern "C" void kernel_launch(void* const* d_in, const int* in_sizes, int n_in,
                              void* d_out, int out_size) {
    const float* x   = (const float*)d_in[0];
    const int*   src = (const int*)d_in[1];
    const int*   dst = (const int*)d_in[2];
    const float* W1s = (const float*)d_in[3];
    const float* W1n = (const float*)d_in[4];
    const float* b1  = (const float*)d_in[5];
    const float* W2s = (const float*)d_in[6];
    const float* W2n = (const float*)d_in[7];
    const float* b2  = (const float*)d_in[8];
    float* out = (float*)d_out;
    int E = in_sizes[1];

    const int smemP = (8192 + 64 * P1) * sizeof(float);            // ~50 KB
    const int smem2 = (2048 + 128 * P2 + 16) * sizeof(float);      // ~43 KB

    // One-time host-side config (outside graph capture: first call is the
    // uncaptured correctness run).
    static cudaStream_t s2 = nullptr;
    static cudaEvent_t  evFork = nullptr, evJoin = nullptr;
    if (s2 == nullptr) {
        cudaFuncSetAttribute(k_proj1,    cudaFuncAttributeMaxDynamicSharedMemorySize, smemP);
        cudaFuncSetAttribute(k_combine2, cudaFuncAttributeMaxDynamicSharedMemorySize, smem2);
        cudaStreamCreateWithFlags(&s2, cudaStreamNonBlocking);
        cudaEventCreateWithFlags(&evFork, cudaEventDisableTiming);
        cudaEventCreateWithFlags(&evJoin, cudaEventDisableTiming);
    }

    int eb4 = (E / 4 + 255) / 256;  // 4 edges per thread kernels

    // Fork: CSR build chain on s2, concurrent with proj1 on the main stream.
    cudaEventRecord(evFork, 0);
    cudaStreamWaitEvent(s2, evFork, 0);

    k_hist<<<eb4, 256, 0, s2>>>(dst, E);
    k_scan<<<NBS, 256, 0, s2>>>();
    k_place<<<eb4, 256, 0, s2>>>(src, dst, E);
    cudaEventRecord(evJoin, s2);

    k_proj1<<<(NN + 63) / 64, 256, smemP>>>(x, W1s, W1n, b1);

    // Join: gather needs both proj1 (main) and CSR (s2).
    cudaStreamWaitEvent(0, evJoin, 0);

    k_gather_h1<<<(NN * 16 + 255) / 256, 256>>>();
    k_combine2<<<(NN + 127) / 128, 256, smem2>>>(W2s, W2n, b2, out);
    k_gather16<<<(NN * 4 + 255) / 256, 256>>>(out);
}

// round 17
// speedup vs baseline: 1.0232x; 1.0232x over previous
#include <cuda_runtime.h>
#include <cuda_fp16.h>
#include <cstdint>

#define NN 100000
#define F1 64
#define F2 16
#define EMAX 1600000
#define NBS 391   // ceil(NN/256)

typedef unsigned long long ull;

// Scratch (allocation-free rule: __device__ globals; zero-init at load,
// re-zeroed by k_gather16's epilogue each call)
__device__ int      g_cnt[NN];
__device__ int      g_off[NN];
__device__ int      g_rank[EMAX];    // per-edge rank within its dst bucket (from hist)
__device__ unsigned g_state[512];    // decoupled-lookback: flag<<30 | value
__device__ int      g_srcs[EMAX];
__device__ __half   g_ynh[NN * F1];  // x @ W1n   (fp16 staged)
__device__ float    g_h1[NN * F1];   // y_s = x@W1s + b1, then overwritten with h1
__device__ __half   g_z2h[NN * F2];  // h1 @ W2n  (fp16 staged)

// ---------------- f32x2 packed helpers (sm_100+) ----------------
__device__ __forceinline__ ull pack2(float v) {
    ull r; asm("mov.b64 %0, {%1, %1};" : "=l"(r) : "f"(v)); return r;
}
__device__ __forceinline__ ull packab(float a, float b) {
    ull r; asm("mov.b64 %0, {%1, %2};" : "=l"(r) : "f"(a), "f"(b)); return r;
}
__device__ __forceinline__ ull fma2(ull a, ull b, ull c) {
    ull d; asm("fma.rn.f32x2 %0, %1, %2, %3;" : "=l"(d) : "l"(a), "l"(b), "l"(c)); return d;
}
__device__ __forceinline__ float2 unpack2(ull v) {
    float2 f; asm("mov.b64 {%0, %1}, %2;" : "=f"(f.x), "=f"(f.y) : "l"(v)); return f;
}
__device__ __forceinline__ unsigned h2u(__half2 h) {
    return *reinterpret_cast<unsigned*>(&h);
}
__device__ __forceinline__ void acc_h4(float4& a, uint2 u) {
    float2 f0 = __half22float2(*reinterpret_cast<__half2*>(&u.x));
    float2 f1 = __half22float2(*reinterpret_cast<__half2*>(&u.y));
    a.x += f0.x; a.y += f0.y; a.z += f1.x; a.w += f1.y;
}
// XOR swizzle on float4 index within a 32-float4 (128-float) row.
__device__ __forceinline__ int swz(int f) { return f ^ ((f >> 3) & 3); }

// ================= in-degree histogram + per-edge rank (4 edges/thread) ====
// g_cnt arrives zeroed (BSS on first call; k_gather16 epilogue afterwards).
__global__ void k_hist(const int* __restrict__ dst, int E) {
    int e0 = (blockIdx.x * 256 + threadIdx.x) * 4;
    if (e0 + 3 < E) {
        int4 d4 = *reinterpret_cast<const int4*>(dst + e0);
        int4 r4;
        r4.x = atomicAdd(&g_cnt[d4.x], 1);
        r4.y = atomicAdd(&g_cnt[d4.y], 1);
        r4.z = atomicAdd(&g_cnt[d4.z], 1);
        r4.w = atomicAdd(&g_cnt[d4.w], 1);
        *reinterpret_cast<int4*>(g_rank + e0) = r4;
    } else {
        for (int e = e0; e < E; ++e) g_rank[e] = atomicAdd(&g_cnt[dst[e]], 1);
    }
}

// ================= single-pass exclusive scan (decoupled lookback) =====
#define SMASK 0x3FFFFFFFu
__global__ void k_scan() {
    __shared__ int sm[256];
    __shared__ int s_prev;
    int b = blockIdx.x, t = threadIdx.x;
    int i = b * 256 + t;
    int v = (i < NN) ? g_cnt[i] : 0;
    sm[t] = v;
    __syncthreads();
    for (int d = 1; d < 256; d <<= 1) {
        int a = (t >= d) ? sm[t - d] : 0;
        __syncthreads();
        sm[t] += a;
        __syncthreads();
    }
    int incl = sm[t];
    if (t == 0) {
        unsigned total = (unsigned)sm[255];
        if (b == 0) {
            atomicExch(&g_state[0], (2u << 30) | total);
            s_prev = 0;
        } else {
            atomicExch(&g_state[b], (1u << 30) | total);
            unsigned prev = 0u;
            int j = b - 1;
            while (true) {
                unsigned st = atomicAdd(&g_state[j], 0u);
                unsigned f = st >> 30;
                if (f == 2u) { prev += st & SMASK; break; }
                if (f == 1u) { prev += st & SMASK; --j; }
            }
            atomicExch(&g_state[b], (2u << 30) | ((prev + total) & SMASK));
            s_prev = (int)prev;
        }
    }
    __syncthreads();
    if (i < NN) g_off[i] = s_prev + incl - v;
}

// ================= bucket placement, ATOMIC-FREE (4 edges/thread) =========
__global__ void k_place(const int* __restrict__ src, const int* __restrict__ dst, int E) {
    int e0 = (blockIdx.x * 256 + threadIdx.x) * 4;
    if (e0 + 3 < E) {
        int4 d4 = *reinterpret_cast<const int4*>(dst + e0);
        int4 s4 = *reinterpret_cast<const int4*>(src + e0);
        int4 r4 = *reinterpret_cast<const int4*>(g_rank + e0);
        g_srcs[g_off[d4.x] + r4.x] = s4.x;
        g_srcs[g_off[d4.y] + r4.y] = s4.y;
        g_srcs[g_off[d4.z] + r4.z] = s4.z;
        g_srcs[g_off[d4.w] + r4.w] = s4.w;
    } else {
        for (int e = e0; e < E; ++e)
            g_srcs[g_off[dst[e]] + g_rank[e]] = src[e];
    }
}

// ================= layer-1 projection GEMM ==================
// y = x[NN x 64] @ [W1s | W1n][64 x 128]. Cols 0..63 -> g_h1 (fp32, bias folded),
// cols 64..127 -> g_ynh (fp16). Weight tile bank-swizzled, loaded ONCE and
// reused for TWO 64-node tiles per block (grid halved -> leaves CTA slots for
// the concurrent CSR chain; R15-measured optimum for the fork section).
#define P1 68
__global__ void __launch_bounds__(256) k_proj1(
    const float* __restrict__ x,
    const float* __restrict__ Ws, const float* __restrict__ Wn,
    const float* __restrict__ b) {
    extern __shared__ float s[];
    float* sW = s;          // 64 x 128, float4-swizzled rows
    float* sX = s + 8192;   // 64 x P1

    int tid = threadIdx.x;

    for (int i = tid; i < 2048; i += 256) {  // 64 rows x 32 float4
        int k = i >> 5, c = i & 31;
        float4 v = (c < 16) ? reinterpret_cast<const float4*>(Ws + k * 64)[c]
                            : reinterpret_cast<const float4*>(Wn + k * 64)[c - 16];
        reinterpret_cast<float4*>(sW + k * 128)[swz(c)] = v;
    }

    int j8 = (tid & 15) << 3;  // 0..120
    int ng = tid >> 4;         // 0..15
    int rb[4] = { ng * P1, (ng + 16) * P1, (ng + 32) * P1, (ng + 48) * P1 };

    int wo0 = 4 * swz(j8 >> 2);
    int wo1 = 4 * swz((j8 >> 2) + 1);

    ull binit[4] = {0ull, 0ull, 0ull, 0ull};
    if (j8 < 64) {
        float4 bl = *reinterpret_cast<const float4*>(b + j8);
        float4 bh = *reinterpret_cast<const float4*>(b + j8 + 4);
        binit[0] = packab(bl.x, bl.y); binit[1] = packab(bl.z, bl.w);
        binit[2] = packab(bh.x, bh.y); binit[3] = packab(bh.z, bh.w);
    }

#pragma unroll 1
    for (int tile = 0; tile < 2; ++tile) {
        int node0 = blockIdx.x * 128 + tile * 64;
        __syncthreads();  // prior tile's mainloop reads done before sX overwrite
        for (int i = tid; i < 64 * 16; i += 256) {
            int row = i >> 4, c = i & 15;
            int n = node0 + row;
            float4 vx = make_float4(0.f, 0.f, 0.f, 0.f);
            if (n < NN) vx = reinterpret_cast<const float4*>(x + (size_t)n * F1)[c];
            *reinterpret_cast<float4*>(sX + row * P1 + 4 * c) = vx;
        }
        __syncthreads();

        ull ac[4][4];
#pragma unroll
        for (int nn = 0; nn < 4; ++nn)
#pragma unroll
            for (int p = 0; p < 4; ++p) ac[nn][p] = binit[p];

#pragma unroll 2
        for (int k0 = 0; k0 < 64; k0 += 4) {
            float4 xv[4];
#pragma unroll
            for (int nn = 0; nn < 4; ++nn)
                xv[nn] = *reinterpret_cast<const float4*>(sX + rb[nn] + k0);
#pragma unroll
            for (int kk = 0; kk < 4; ++kk) {
                const float* wrow = sW + (k0 + kk) * 128;
                ulonglong2 wA = *reinterpret_cast<const ulonglong2*>(wrow + wo0);
                ulonglong2 wB = *reinterpret_cast<const ulonglong2*>(wrow + wo1);
#pragma unroll
                for (int nn = 0; nn < 4; ++nn) {
                    float xs = (kk == 0) ? xv[nn].x : (kk == 1) ? xv[nn].y
                             : (kk == 2) ? xv[nn].z : xv[nn].w;
                    ull xx = pack2(xs);
                    ac[nn][0] = fma2(xx, wA.x, ac[nn][0]);
                    ac[nn][1] = fma2(xx, wA.y, ac[nn][1]);
                    ac[nn][2] = fma2(xx, wB.x, ac[nn][2]);
                    ac[nn][3] = fma2(xx, wB.y, ac[nn][3]);
                }
            }
        }

        if (j8 < 64) {
#pragma unroll
            for (int nn = 0; nn < 4; ++nn) {
                int gn = node0 + ng + nn * 16;
                if (gn < NN) {
                    float2 r0 = unpack2(ac[nn][0]), r1 = unpack2(ac[nn][1]);
                    float2 r2 = unpack2(ac[nn][2]), r3 = unpack2(ac[nn][3]);
                    float4 o0 = make_float4(r0.x, r0.y, r1.x, r1.y);
                    float4 o1 = make_float4(r2.x, r2.y, r3.x, r3.y);
                    *reinterpret_cast<float4*>(g_h1 + (size_t)gn * F1 + j8)     = o0;
                    *reinterpret_cast<float4*>(g_h1 + (size_t)gn * F1 + j8 + 4) = o1;
                }
            }
        } else {
            int jc = j8 - 64;
#pragma unroll
            for (int nn = 0; nn < 4; ++nn) {
                int gn = node0 + ng + nn * 16;
                if (gn < NN) {
                    float2 r0 = unpack2(ac[nn][0]), r1 = unpack2(ac[nn][1]);
                    float2 r2 = unpack2(ac[nn][2]), r3 = unpack2(ac[nn][3]);
                    uint4 st = make_uint4(h2u(__float22half2_rn(r0)),
                                          h2u(__float22half2_rn(r1)),
                                          h2u(__float22half2_rn(r2)),
                                          h2u(__float22half2_rn(r3)));
                    *reinterpret_cast<uint4*>(g_ynh + (size_t)gn * F1 + jc) = st;
                }
            }
        }
    }
}

// ================= layer-1 gather + epilogue ==================
// h1[n] = relu(y_s[n] + (sum ynh[src]) / deg). 16 threads/node, 4 halves each.
__global__ void k_gather_h1() {
    int t = blockIdx.x * 256 + threadIdx.x;
    int n = t >> 4;
    if (n >= NN) return;
    int c4 = (t & 15) << 2;
    int base = g_off[n], cnt = g_cnt[n];
    float4 a = make_float4(0.f, 0.f, 0.f, 0.f);
    int i = 0;
#pragma unroll 2
    for (; i + 4 <= cnt; i += 4) {
        int s0 = g_srcs[base + i];
        int s1 = g_srcs[base + i + 1];
        int s2 = g_srcs[base + i + 2];
        int s3 = g_srcs[base + i + 3];
        uint2 v0 = *reinterpret_cast<const uint2*>(g_ynh + (size_t)s0 * F1 + c4);
        uint2 v1 = *reinterpret_cast<const uint2*>(g_ynh + (size_t)s1 * F1 + c4);
        uint2 v2 = *reinterpret_cast<const uint2*>(g_ynh + (size_t)s2 * F1 + c4);
        uint2 v3 = *reinterpret_cast<const uint2*>(g_ynh + (size_t)s3 * F1 + c4);
        acc_h4(a, v0); acc_h4(a, v1); acc_h4(a, v2); acc_h4(a, v3);
    }
    for (; i < cnt; ++i) {
        int s0 = g_srcs[base + i];
        acc_h4(a, *reinterpret_cast<const uint2*>(g_ynh + (size_t)s0 * F1 + c4));
    }
    float dinv = 1.0f / (float)max(cnt, 1);
    float* p = g_h1 + (size_t)n * F1 + c4;
    float4 ys = *reinterpret_cast<const float4*>(p);
    float4 o;
    o.x = fmaxf(fmaf(a.x, dinv, ys.x), 0.f);
    o.y = fmaxf(fmaf(a.y, dinv, ys.y), 0.f);
    o.z = fmaxf(fmaf(a.z, dinv, ys.z), 0.f);
    o.w = fmaxf(fmaf(a.w, dinv, ys.w), 0.f);
    *reinterpret_cast<float4*>(p) = o;
}

// ================= layer-2 combine: GEMM [NN x 64] @ [64 x 32] =========
// Cols 0..15 -> out (self + bias, fp32), cols 16..31 -> g_z2h (fp16).
#define P2 68
__global__ void __launch_bounds__(256) k_combine2(
    const float* __restrict__ Ws, const float* __restrict__ Wn,
    const float* __restrict__ b, float* __restrict__ out) {
    extern __shared__ float s[];
    float* sW = s;         // 64 x 32
    float* sH = s + 2048;  // 128 x P2
    float* sB = s + 2048 + 128 * P2;  // 16

    int tid   = threadIdx.x;
    int node0 = blockIdx.x * 128;

    {
        int k = tid >> 2, c = tid & 3;
        reinterpret_cast<float4*>(sW + k * 32)[c]      = reinterpret_cast<const float4*>(Ws + k * 16)[c];
        reinterpret_cast<float4*>(sW + k * 32 + 16)[c] = reinterpret_cast<const float4*>(Wn + k * 16)[c];
    }
    if (tid < 16) sB[tid] = b[tid];
    for (int i = tid; i < 128 * 16; i += 256) {
        int row = i >> 4, c = i & 15;
        int n = node0 + row;
        float4 v = make_float4(0.f, 0.f, 0.f, 0.f);
        if (n < NN) v = reinterpret_cast<const float4*>(g_h1 + (size_t)n * F1)[c];
        *reinterpret_cast<float4*>(sH + row * P2 + 4 * c) = v;
    }
    __syncthreads();

    int j8 = (tid & 3) << 3;  // 0,8,16,24
    int ng = tid >> 2;        // 0..63
    int rb[2] = { ng * P2, (ng + 64) * P2 };

    ull ac[2][4];
#pragma unroll
    for (int nn = 0; nn < 2; ++nn)
#pragma unroll
        for (int p = 0; p < 4; ++p) ac[nn][p] = 0ull;

#pragma unroll 4
    for (int k = 0; k < 64; ++k) {
        const float* wp = sW + k * 32 + j8;
        ulonglong2 wA = *reinterpret_cast<const ulonglong2*>(wp);
        ulonglong2 wB = *reinterpret_cast<const ulonglong2*>(wp + 4);
#pragma unroll
        for (int nn = 0; nn < 2; ++nn) {
            ull hh = pack2(sH[rb[nn] + k]);
            ac[nn][0] = fma2(hh, wA.x, ac[nn][0]);
            ac[nn][1] = fma2(hh, wA.y, ac[nn][1]);
            ac[nn][2] = fma2(hh, wB.x, ac[nn][2]);
            ac[nn][3] = fma2(hh, wB.y, ac[nn][3]);
        }
    }

    if (j8 < 16) {
        float4 bl = *reinterpret_cast<const float4*>(sB + j8);
        float4 bh = *reinterpret_cast<const float4*>(sB + j8 + 4);
#pragma unroll
        for (int nn = 0; nn < 2; ++nn) {
            int gn = node0 + ng + nn * 64;
            if (gn < NN) {
                float2 r0 = unpack2(ac[nn][0]), r1 = unpack2(ac[nn][1]);
                float2 r2 = unpack2(ac[nn][2]), r3 = unpack2(ac[nn][3]);
                float4 o0 = make_float4(r0.x + bl.x, r0.y + bl.y, r1.x + bl.z, r1.y + bl.w);
                float4 o1 = make_float4(r2.x + bh.x, r2.y + bh.y, r3.x + bh.z, r3.y + bh.w);
                *reinterpret_cast<float4*>(out + (size_t)gn * F2 + j8)     = o0;
                *reinterpret_cast<float4*>(out + (size_t)gn * F2 + j8 + 4) = o1;
            }
        }
    } else {
        int j = j8 - 16;
#pragma unroll
        for (int nn = 0; nn < 2; ++nn) {
            int gn = node0 + ng + nn * 64;
            if (gn < NN) {
                float2 r0 = unpack2(ac[nn][0]), r1 = unpack2(ac[nn][1]);
                float2 r2 = unpack2(ac[nn][2]), r3 = unpack2(ac[nn][3]);
                uint4 st = make_uint4(h2u(__float22half2_rn(r0)),
                                      h2u(__float22half2_rn(r1)),
                                      h2u(__float22half2_rn(r2)),
                                      h2u(__float22half2_rn(r3)));
                *reinterpret_cast<uint4*>(g_z2h + (size_t)gn * F2 + j) = st;
            }
        }
    }
}

// ================= layer-2 gather + finalize + scratch re-zero ============
__global__ void k_gather16(float* __restrict__ out) {
    int t = blockIdx.x * 256 + threadIdx.x;
    // re-zero lookback state for the NEXT invocation
    if (blockIdx.x == 0 && threadIdx.x < 512) g_state[threadIdx.x] = 0u;
    int n = t >> 2;
    if (n >= NN) return;
    int c4 = (t & 3) << 2;
    int base = g_off[n], cnt = g_cnt[n];
    float4 a = make_float4(0.f, 0.f, 0.f, 0.f);
    int i = 0;
#pragma unroll 2
    for (; i + 4 <= cnt; i += 4) {
        int s0 = g_srcs[base + i];
        int s1 = g_srcs[base + i + 1];
        int s2 = g_srcs[base + i + 2];
        int s3 = g_srcs[base + i + 3];
        uint2 v0 = *reinterpret_cast<const uint2*>(g_z2h + (size_t)s0 * F2 + c4);
        uint2 v1 = *reinterpret_cast<const uint2*>(g_z2h + (size_t)s1 * F2 + c4);
        uint2 v2 = *reinterpret_cast<const uint2*>(g_z2h + (size_t)s2 * F2 + c4);
        uint2 v3 = *reinterpret_cast<const uint2*>(g_z2h + (size_t)s3 * F2 + c4);
        acc_h4(a, v0); acc_h4(a, v1); acc_h4(a, v2); acc_h4(a, v3);
    }
    for (; i < cnt; ++i) {
        int s0 = g_srcs[base + i];
        acc_h4(a, *reinterpret_cast<const uint2*>(g_z2h + (size_t)s0 * F2 + c4));
    }
    // re-zero g_cnt[n] for the next invocation (cnt already read by all 4
    // lanes of this node, same warp, before this store)
    if ((t & 3) == 0) g_cnt[n] = 0;
    float dinv = 1.0f / (float)max(cnt, 1);
    float4 o = *reinterpret_cast<float4*>(out + (size_t)n * F2 + c4);
    o.x = fmaf(a.x, dinv, o.x); o.y = fmaf(a.y, dinv, o.y);
    o.z = fmaf(a.z, dinv, o.z); o.w = fmaf(a.w, dinv, o.w);
    *reinterpret_cast<float4*>(out + (size_t)n * F2 + c4) = o;
}

extern "C" void kernel_launch(void* const* d_in, const int* in_sizes, int n_in,
                              void* d_out, int out_size) {
    const float* x   = (const float*)d_in[0];
    const int*   src = (const int*)d_in[1];
    const int*   dst = (const int*)d_in[2];
    const float* W1s = (const float*)d_in[3];
    const float* W1n = (const float*)d_in[4];
    const float* b1  = (const float*)d_in[5];
    const float* W2s = (const float*)d_in[6];
    const float* W2n = (const float*)d_in[7];
    const float* b2  = (const float*)d_in[8];
    float* out = (float*)d_out;
    int E = in_sizes[1];

    const int smemP = (8192 + 64 * P1) * sizeof(float);            // ~50 KB
    const int smem2 = (2048 + 128 * P2 + 16) * sizeof(float);      // ~43 KB

    // One-time host-side config (outside graph capture: first call is the
    // uncaptured correctness run). s2 gets GREATEST priority so the
    // latency-bound CSR chain claims CTA slots ahead of proj1's flood.
    static cudaStream_t s2 = nullptr;
    static cudaEvent_t  evFork = nullptr, evJoin = nullptr;
    if (s2 == nullptr) {
        cudaFuncSetAttribute(k_proj1,    cudaFuncAttributeMaxDynamicSharedMemorySize, smemP);
        cudaFuncSetAttribute(k_combine2, cudaFuncAttributeMaxDynamicSharedMemorySize, smem2);
        int prLo, prHi;
        cudaDeviceGetStreamPriorityRange(&prLo, &prHi);
        cudaStreamCreateWithPriority(&s2, cudaStreamNonBlocking, prHi);
        cudaEventCreateWithFlags(&evFork, cudaEventDisableTiming);
        cudaEventCreateWithFlags(&evJoin, cudaEventDisableTiming);
    }

    int eb4 = (E / 4 + 255) / 256;  // 4 edges per thread kernels

    // Fork: CSR build chain on s2 (high priority), concurrent with proj1.
    cudaEventRecord(evFork, 0);
    cudaStreamWaitEvent(s2, evFork, 0);

    k_hist<<<eb4, 256, 0, s2>>>(dst, E);
    k_scan<<<NBS, 256, 0, s2>>>();
    k_place<<<eb4, 256, 0, s2>>>(src, dst, E);
    cudaEventRecord(evJoin, s2);

    k_proj1<<<(NN + 127) / 128, 256, smemP>>>(x, W1s, W1n, b1);

    // Join: gather needs both proj1 (main) and CSR (s2).
    cudaStreamWaitEvent(0, evJoin, 0);

    k_gather_h1<<<(NN * 16 + 255) / 256, 256>>>();
    k_combine2<<<(NN + 127) / 128, 256, smem2>>>(W2s, W2n, b2, out);
    k_gather16<<<(NN * 4 + 255) / 256, 256>>>(out);
}